// round 12
// baseline (speedup 1.0000x reference)
#include <cuda_runtime.h>
#include <math.h>
#include <cstdint>

#define BB 256
#define TT 256
#define DD 64
#define HH 256
#define G3 768   // 3*H
#define NBLK 128

// ---------------- device scratch (allocation-free) ----------------
__device__ float g_gi0[2ull * TT * BB * G3];
__device__ float g_gi1[2ull * TT * BB * G3];
__device__ float g_y0 [2ull * TT * BB * HH];
__device__ float g_y1 [2ull * TT * BB * HH];
__device__ unsigned g_ctrs[8];   // per-group step counters (zero-init)
__device__ unsigned g_ctre[8];   // per-group exit counters (zero-init)

// ================= mma.sync tf32 helpers (sm_80+, family-agnostic) ========
__device__ __forceinline__ uint32_t f2tf32(float f) {
    uint32_t r;
    asm("cvt.rna.tf32.f32 %0, %1;" : "=r"(r) : "f"(f));
    return r;
}
__device__ __forceinline__ void mma1688(float* d, const uint32_t* a, const uint32_t* b) {
    asm volatile(
        "mma.sync.aligned.m16n8k8.row.col.f32.tf32.tf32.f32 "
        "{%0,%1,%2,%3}, {%4,%5,%6,%7}, {%8,%9}, {%0,%1,%2,%3};"
        : "+f"(d[0]), "+f"(d[1]), "+f"(d[2]), "+f"(d[3])
        : "r"(a[0]), "r"(a[1]), "r"(a[2]), "r"(a[3]), "r"(b[0]), "r"(b[1]));
}

// =================================================================
// gi GEMM via mma.sync tf32, tile M=128 x N=128 (v2).
// 8 warps = 4m x 2n; warp tile 32m x 64n = 2 mfrag x 8 nfrag.
// Per kk8: 16 MMA vs 24 fragment-LDS (was 8 vs 16) and A re-read 6x (was 12x).
// MODE 0: A = x[b][t][k] (KDIM=64)  -> g_gi0
// MODE 1: A = concat(yf0,yb0)[t][b][k] (KDIM=512) -> g_gi1
// =================================================================
#define KC 32
#define AP 36

template<int KDIM, int MODE>
__global__ __launch_bounds__(256)
void gi_mma_kernel(const float* __restrict__ x,
                   const float* __restrict__ w_ih,   // [2][G3][KDIM]
                   const float* __restrict__ b_ih)   // [2][G3]
{
    __shared__ uint32_t as[128 * AP];    // A tile (tf32 bits)
    __shared__ uint32_t wsm[128 * AP];   // W tile (tf32 bits)

    const int tid  = threadIdx.x;
    const int wid  = tid >> 5;
    const int lane = tid & 31;
    const int g    = lane >> 2;
    const int tig  = lane & 3;

    const int bx  = blockIdx.x;
    const int t   = bx >> 1;
    const int b0  = (bx & 1) * 128;
    const int n0  = blockIdx.y * 128;
    const int dir = blockIdx.z;

    const int wm = wid >> 1;        // 0..3: 32-row m sub-tile
    const int wn = wid & 1;         // 0..1: 64-col n sub-tile

    const float* wdir = w_ih + (size_t)dir * G3 * KDIM;

    float acc[2][8][4];
#pragma unroll
    for (int mf = 0; mf < 2; mf++)
#pragma unroll
        for (int nf = 0; nf < 8; nf++)
#pragma unroll
            for (int q = 0; q < 4; q++) acc[mf][nf][q] = 0.f;

    for (int c = 0; c < KDIM / KC; c++) {
        const int koff = c * KC;

        // ---- stage A: 128 rows x 32 k (4 float4 per thread) ----
#pragma unroll
        for (int i = 0; i < 4; i++) {
            int idx = tid + 256 * i;     // 0..1023
            int row = idx >> 3;
            int kq  = (idx & 7) * 4;
            float4 v;
            if (MODE == 0) {
                v = *(const float4*)(x + ((size_t)(b0 + row) * TT + t) * DD + koff + kq);
            } else {
                int k = koff + kq;
                if (k < HH)
                    v = *(const float4*)(g_y0 + ((size_t)t * BB + b0 + row) * HH + k);
                else
                    v = *(const float4*)(g_y0 + (size_t)TT * BB * HH +
                                         ((size_t)t * BB + b0 + row) * HH + (k - HH));
            }
            uint32_t* p = &as[row * AP + kq];
            p[0] = f2tf32(v.x); p[1] = f2tf32(v.y);
            p[2] = f2tf32(v.z); p[3] = f2tf32(v.w);
        }
        // ---- stage W: 128 rows x 32 k (4 float4 per thread) ----
#pragma unroll
        for (int i = 0; i < 4; i++) {
            int idx = tid + 256 * i;
            int row = idx >> 3;
            int kq  = (idx & 7) * 4;
            float4 v = *(const float4*)(wdir + (size_t)(n0 + row) * KDIM + koff + kq);
            uint32_t* p = &wsm[row * AP + kq];
            p[0] = f2tf32(v.x); p[1] = f2tf32(v.y);
            p[2] = f2tf32(v.z); p[3] = f2tf32(v.w);
        }
        __syncthreads();

#pragma unroll
        for (int kk = 0; kk < KC; kk += 8) {
            uint32_t afr[2][4], bfr[8][2];
#pragma unroll
            for (int mf = 0; mf < 2; mf++) {
                int base = wm * 32 + mf * 16;
                afr[mf][0] = as[(base + g)     * AP + kk + tig];
                afr[mf][1] = as[(base + g + 8) * AP + kk + tig];
                afr[mf][2] = as[(base + g)     * AP + kk + tig + 4];
                afr[mf][3] = as[(base + g + 8) * AP + kk + tig + 4];
            }
#pragma unroll
            for (int nf = 0; nf < 8; nf++) {
                int nb = wn * 64 + nf * 8;
                bfr[nf][0] = wsm[(nb + g) * AP + kk + tig];
                bfr[nf][1] = wsm[(nb + g) * AP + kk + tig + 4];
            }
#pragma unroll
            for (int mf = 0; mf < 2; mf++)
#pragma unroll
                for (int nf = 0; nf < 8; nf++)
                    mma1688(acc[mf][nf], afr[mf], bfr[nf]);
        }
        __syncthreads();
    }

    // ---- epilogue: bias + store ----
    float* gout = (MODE == 0) ? g_gi0 : g_gi1;
    const float* bias = b_ih + dir * G3;

#pragma unroll
    for (int mf = 0; mf < 2; mf++) {
#pragma unroll
        for (int rs = 0; rs < 2; rs++) {
            int mloc = wm * 32 + mf * 16 + g + rs * 8;
            int b = b0 + mloc;
            float* orow = gout + (((size_t)dir * TT + t) * BB + b) * G3 + n0;
#pragma unroll
            for (int nf = 0; nf < 8; nf++) {
                int col = wn * 64 + nf * 8 + 2 * tig;
                float2 o;
                o.x = acc[mf][nf][rs * 2 + 0] + bias[n0 + col];
                o.y = acc[mf][nf][rs * 2 + 1] + bias[n0 + col + 1];
                *(float2*)(orow + col) = o;
            }
        }
    }
}

// =================================================================
// Persistent per-layer recurrence kernel (exact R8 structure — proven).
// Grid = 128 blocks (dir | b-tile(64) | j-tile(16)), 256 thr = 8 warps.
// Warp = (wm: 16 b-rows) x (wn: 8 j x 3 gates); h staged as tf32 hi/lo,
// 6 MMAs per kk (A effectively fp32). 16-block barrier groups.
// =================================================================
#define HSP 260
#define WSF_BYTES (3 * 2 * 32 * 32 * 8)         // 49152
#define HS_BYTES  (64 * HSP * 4)                 // 66560
#define LAYER_SMEM (WSF_BYTES + 2 * HS_BYTES)    // 182272

template<int LAYER>
__global__ __launch_bounds__(256)
void layer_kernel(const float* __restrict__ w_hh,   // [2][G3][H]
                  const float* __restrict__ b_hh)   // [2][G3]
{
    extern __shared__ char smraw[];
    uint2*    wsf   = (uint2*)smraw;
    uint32_t* hs_hi = (uint32_t*)(smraw + WSF_BYTES);
    uint32_t* hs_lo = (uint32_t*)(smraw + WSF_BYTES + HS_BYTES);

    const int bid = blockIdx.x;
    const int dir = bid >> 6;
    const int rr  = bid & 63;
    const int j0  = (rr & 15) * 16;
    const int b0  = (rr >> 4) * 64;
    const int grp = bid >> 4;

    const int tid  = threadIdx.x;
    const int wid  = tid >> 5;
    const int lane = tid & 31;
    const int g    = lane >> 2;
    const int tig  = lane & 3;
    const int wm   = wid >> 1;      // 0..3: m sub-tile (16 rows)
    const int wn   = wid & 1;       // 0..1: j half (8 cols)

    const float* gi = LAYER ? g_gi1 : g_gi0;
    float*       y  = LAYER ? g_y1  : g_y0;
    const float* w  = w_hh + (size_t)dir * G3 * HH;
    const float* bh = b_hh + dir * G3;

    // ---- pack weight fragments once ----
    for (int e = tid; e < 3 * 2 * 32 * 32; e += 256) {
        int el = e & 31;
        int kk = (e >> 5) & 31;
        int ww = (e >> 10) & 1;
        int g3 = e >> 11;
        int j  = j0 + ww * 8 + (el >> 2);
        int k0 = kk * 8 + (el & 3);
        const float* wr = w + (size_t)(g3 * HH + j) * HH;
        uint2 bv;
        bv.x = f2tf32(wr[k0]);
        bv.y = f2tf32(wr[k0 + 4]);
        wsf[e] = bv;
    }

    const int jj = wn * 8 + 2 * tig;
    const int jglob = j0 + jj;
    float2 bhr = *(const float2*)&bh[jglob];
    float2 bhz = *(const float2*)&bh[HH + jglob];
    float2 bhn = *(const float2*)&bh[2 * HH + jglob];

    __syncthreads();

    volatile unsigned* vc = &g_ctrs[grp];
    const uint2* wsf_w = wsf + (size_t)wn * 1024;
    const int r0 = wm * 16;

    for (int t = 0; t < TT; t++) {
        const int teff = (dir == 0) ? t : (TT - 1 - t);
        const float* gi_t = gi + ((size_t)(dir * TT + teff) * BB) * G3;
        float*       y_t  = y  + ((size_t)(dir * TT + teff) * BB) * HH;

        float acc[3][4];
#pragma unroll
        for (int g3 = 0; g3 < 3; g3++)
#pragma unroll
            for (int q = 0; q < 4; q++) acc[g3][q] = 0.f;

        if (t > 0) {
            const int tprev = (dir == 0) ? (teff - 1) : (teff + 1);
            const float* h_prev = y + ((size_t)(dir * TT + tprev) * BB) * HH;

            // ---- stage h slice as tf32 hi/lo ----
#pragma unroll
            for (int it = 0; it < 16; it++) {
                int idx = tid + 256 * it;      // 0..4095
                int kq  = idx & 63;
                int b   = idx >> 6;
                float4 v = *(const float4*)(h_prev + (size_t)(b0 + b) * HH + kq * 4);
                uint4 hi, lo;
                hi.x = f2tf32(v.x); lo.x = f2tf32(v.x - __uint_as_float(hi.x));
                hi.y = f2tf32(v.y); lo.y = f2tf32(v.y - __uint_as_float(hi.y));
                hi.z = f2tf32(v.z); lo.z = f2tf32(v.z - __uint_as_float(hi.z));
                hi.w = f2tf32(v.w); lo.w = f2tf32(v.w - __uint_as_float(hi.w));
                *(uint4*)&hs_hi[b * HSP + kq * 4] = hi;
                *(uint4*)&hs_lo[b * HSP + kq * 4] = lo;
            }
            __syncthreads();

            // ---- tensor k-loop: 32 x k8, 2 MMAs (hi+lo) x 3 gates ----
#pragma unroll 4
            for (int kk = 0; kk < 32; kk++) {
                int ko = kk * 8;
                uint32_t ahi[4], alo[4];
                ahi[0] = hs_hi[(r0 + g)     * HSP + ko + tig];
                ahi[1] = hs_hi[(r0 + g + 8) * HSP + ko + tig];
                ahi[2] = hs_hi[(r0 + g)     * HSP + ko + tig + 4];
                ahi[3] = hs_hi[(r0 + g + 8) * HSP + ko + tig + 4];
                alo[0] = hs_lo[(r0 + g)     * HSP + ko + tig];
                alo[1] = hs_lo[(r0 + g + 8) * HSP + ko + tig];
                alo[2] = hs_lo[(r0 + g)     * HSP + ko + tig + 4];
                alo[3] = hs_lo[(r0 + g + 8) * HSP + ko + tig + 4];
#pragma unroll
                for (int g3 = 0; g3 < 3; g3++) {
                    uint2 bv = wsf_w[g3 * 2048 + kk * 32 + lane];
                    uint32_t bf[2] = {bv.x, bv.y};
                    mma1688(acc[g3], ahi, bf);
                    mma1688(acc[g3], alo, bf);
                }
            }
        }

        // ---- gate math + store: 2 row-halves x 2 j cols per thread ----
#pragma unroll
        for (int rs = 0; rs < 2; rs++) {
            const int rl = r0 + g + rs * 8;          // local row
            const int b  = b0 + rl;                  // global batch row
            const float* girow = gi_t + (size_t)b * G3;
            float2 gir = *(const float2*)&girow[jglob];
            float2 giz = *(const float2*)&girow[HH + jglob];
            float2 gin = *(const float2*)&girow[2 * HH + jglob];

            float hp0 = 0.f, hp1 = 0.f;
            if (t > 0) {
                hp0 = __uint_as_float(hs_hi[rl * HSP + jglob]) +
                      __uint_as_float(hs_lo[rl * HSP + jglob]);
                hp1 = __uint_as_float(hs_hi[rl * HSP + jglob + 1]) +
                      __uint_as_float(hs_lo[rl * HSP + jglob + 1]);
            }

            float ar0 = acc[0][rs * 2 + 0] + bhr.x;
            float ar1 = acc[0][rs * 2 + 1] + bhr.y;
            float az0 = acc[1][rs * 2 + 0] + bhz.x;
            float az1 = acc[1][rs * 2 + 1] + bhz.y;
            float an0 = acc[2][rs * 2 + 0] + bhn.x;
            float an1 = acc[2][rs * 2 + 1] + bhn.y;

            float rv0 = 1.f / (1.f + expf(-(gir.x + ar0)));
            float rv1 = 1.f / (1.f + expf(-(gir.y + ar1)));
            float zv0 = 1.f / (1.f + expf(-(giz.x + az0)));
            float zv1 = 1.f / (1.f + expf(-(giz.y + az1)));
            float nv0 = tanhf(gin.x + rv0 * an0);
            float nv1 = tanhf(gin.y + rv1 * an1);

            float2 o;
            o.x = (1.f - zv0) * nv0 + zv0 * hp0;
            o.y = (1.f - zv1) * nv1 + zv1 * hp1;
            *(float2*)(y_t + (size_t)b * HH + jglob) = o;
        }

        // ---- group barrier (16 blocks sharing (dir, b-tile)) ----
        if (t < TT - 1) {
            __syncthreads();
            if (tid == 0) {
                __threadfence();
                atomicAdd(&g_ctrs[grp], 1);
                unsigned target = (unsigned)(t + 1) * 16;
                while (*vc < target) { }
                __threadfence();
            }
            __syncthreads();
        }
    }

    // deadlock-safe per-group counter reset for graph replay
    __syncthreads();
    if (tid == 0) {
        atomicAdd(&g_ctre[grp], 1);
        if ((bid & 15) == 0) {
            volatile unsigned* ve = &g_ctre[grp];
            while (*ve < 16) { }
            *(volatile unsigned*)&g_ctrs[grp] = 0;
            *(volatile unsigned*)&g_ctre[grp] = 0;
            __threadfence();
        }
    }
}

// =================================================================
// Gather: out[b][0:H] = y1_fwd[T-1][b], out[b][H:2H] = y1_bwd[0][b]
// =================================================================
__global__ void gather_kernel(float* __restrict__ out)
{
    int idx = blockIdx.x * blockDim.x + threadIdx.x;
    int b = idx >> 9;
    int j = idx & 511;
    float v;
    if (j < HH)
        v = g_y1[(((size_t)0 * TT + (TT - 1)) * BB + b) * HH + j];
    else
        v = g_y1[(((size_t)1 * TT + 0) * BB + b) * HH + (j - HH)];
    out[idx] = v;
}

// =================================================================
extern "C" void kernel_launch(void* const* d_in, const int* in_sizes, int n_in,
                              void* d_out, int out_size)
{
    const float* x     = (const float*)d_in[0];
    const float* w_ih0 = (const float*)d_in[1];
    const float* w_hh0 = (const float*)d_in[2];
    const float* b_ih0 = (const float*)d_in[3];
    const float* b_hh0 = (const float*)d_in[4];
    const float* w_ih1 = (const float*)d_in[5];
    const float* w_hh1 = (const float*)d_in[6];
    const float* b_ih1 = (const float*)d_in[7];
    const float* b_hh1 = (const float*)d_in[8];
    float* out = (float*)d_out;

    cudaFuncSetAttribute(layer_kernel<0>,
                         cudaFuncAttributeMaxDynamicSharedMemorySize, LAYER_SMEM);
    cudaFuncSetAttribute(layer_kernel<1>,
                         cudaFuncAttributeMaxDynamicSharedMemorySize, LAYER_SMEM);

    dim3 mma_grid(512, 6, 2);   // m-tiles(65536/128), n-tiles(768/128), dirs

    gi_mma_kernel<DD, 0><<<mma_grid, 256>>>(x, w_ih0, b_ih0);
    layer_kernel<0><<<NBLK, 256, LAYER_SMEM>>>(w_hh0, b_hh0);
    gi_mma_kernel<2 * HH, 1><<<mma_grid, 256>>>(nullptr, w_ih1, b_ih1);
    layer_kernel<1><<<NBLK, 256, LAYER_SMEM>>>(w_hh1, b_hh1);
    gather_kernel<<<512, 256>>>(out);
}